// round 1
// baseline (speedup 1.0000x reference)
#include <cuda_runtime.h>

#define K_CODES 16384
#define N_ROWS  8192
#define CAP     128
#define TK      256

// ---------------- scratch (__device__ globals: no allocs allowed) -------------
__device__ float g_cbp[9 * K_CODES];     // SoA: j<8 -> -2*e_j[k]; j==8 -> sum e^2
__device__ float g_S1[N_ROWS];
__device__ float g_S2[N_ROWS];
__device__ int   g_cnt[N_ROWS];
__device__ int   g_idx[N_ROWS];
__device__ float g_avg[K_CODES];
__device__ int   g_candk[N_ROWS * CAP];
__device__ float g_cande[N_ROWS * CAP];
__device__ float g_sampleH;
__device__ float g_mse;

// ---------------- f32x2 helpers ----------------------------------------------
static __device__ __forceinline__ unsigned long long pk2(float a, float b) {
    unsigned long long r;
    asm("mov.b64 %0, {%1, %2};" : "=l"(r) : "f"(a), "f"(b));
    return r;
}
static __device__ __forceinline__ void upk2(unsigned long long v, float& a, float& b) {
    asm("mov.b64 {%0, %1}, %2;" : "=f"(a), "=f"(b) : "l"(v));
}
static __device__ __forceinline__ unsigned long long ffma2(
    unsigned long long a, unsigned long long b, unsigned long long c) {
    unsigned long long d;
    asm("fma.rn.f32x2 %0, %1, %2, %3;" : "=l"(d) : "l"(a), "l"(b), "l"(c));
    return d;
}

// ---------------- pass 0: zero scratch ----------------------------------------
__global__ void k_zero() {
    int t = blockIdx.x * blockDim.x + threadIdx.x;
    if (t < K_CODES) g_avg[t] = 0.f;
    if (t < N_ROWS) {
        g_S1[t] = 0.f; g_S2[t] = 0.f; g_cnt[t] = 0; g_idx[t] = 0x7fffffff;
    }
    if (t == 0) { g_sampleH = 0.f; g_mse = 0.f; }
}

// ---------------- pass 0b: preprocess codebook to SoA {-2e, ee} ---------------
__global__ void k_prep(const float* __restrict__ cb) {
    int k = blockIdx.x * blockDim.x + threadIdx.x;
    if (k >= K_CODES) return;
    float ss = 0.f;
#pragma unroll
    for (int j = 0; j < 8; j++) {
        float e = cb[k * 8 + j];
        g_cbp[j * K_CODES + k] = -2.f * e;
        ss += e * e;
    }
    g_cbp[8 * K_CODES + k] = ss;
}

// ---------------- main: 2 sweeps over K (argmin-value, then sparse softmax) ---
// block: 256 thr (8 warps), 8 rows per warp -> 64 rows/block, grid 128.
__global__ __launch_bounds__(256, 1) void k_main(const float* __restrict__ z) {
    __shared__ __align__(16) float s_cb[9][2 * TK];  // values duplicated for LDS.64
    __shared__ float s_z[64 * 8];

    const int tid  = threadIdx.x;
    const int lane = tid & 31;
    const int w    = tid >> 5;
    const int rowBase = blockIdx.x * 64;

    // stage this block's 64 z-rows (row-major [row][feat]) into smem
    for (int i = tid; i < 512; i += 256) {
        int ro = i >> 3, j = i & 7;
        int row = rowBase + ro;
        s_z[i] = z[(row >> 8) * 2048 + j * 256 + (row & 255)];
    }
    __syncthreads();

    // pack z row-pairs: z2[p][j] = {z[2p][j], z[2p+1][j]} for this warp's 8 rows
    unsigned long long z2[4][8];
#pragma unroll
    for (int p = 0; p < 4; p++)
#pragma unroll
        for (int j = 0; j < 8; j++)
            z2[p][j] = pk2(s_z[(w * 8 + 2 * p) * 8 + j],
                           s_z[(w * 8 + 2 * p + 1) * 8 + j]);

    float dmin[8];
#pragma unroll
    for (int r = 0; r < 8; r++) dmin[r] = 3.4e38f;

    // ---------------- sweep 1: packed running min (no index) ------------------
    for (int tile = 0; tile < K_CODES / TK; ++tile) {
        __syncthreads();
#pragma unroll
        for (int j = 0; j < 9; j++) {
            float v = g_cbp[j * K_CODES + tile * TK + tid];
            ((float2*)s_cb[j])[tid] = make_float2(v, v);
        }
        __syncthreads();
#pragma unroll 2
        for (int s = 0; s < TK / 32; s++) {
            int off = (s * 32 + lane) * 2;
            unsigned long long ee2 = *(const unsigned long long*)&s_cb[8][off];
            unsigned long long a0 = ee2, a1 = ee2, a2 = ee2, a3 = ee2;
#pragma unroll
            for (int j = 0; j < 8; j++) {
                unsigned long long ej = *(const unsigned long long*)&s_cb[j][off];
                a0 = ffma2(z2[0][j], ej, a0);
                a1 = ffma2(z2[1][j], ej, a1);
                a2 = ffma2(z2[2][j], ej, a2);
                a3 = ffma2(z2[3][j], ej, a3);
            }
            float d0, d1, d2, d3, d4, d5, d6, d7;
            upk2(a0, d0, d1); upk2(a1, d2, d3);
            upk2(a2, d4, d5); upk2(a3, d6, d7);
            dmin[0] = fminf(dmin[0], d0); dmin[1] = fminf(dmin[1], d1);
            dmin[2] = fminf(dmin[2], d2); dmin[3] = fminf(dmin[3], d3);
            dmin[4] = fminf(dmin[4], d4); dmin[5] = fminf(dmin[5], d5);
            dmin[6] = fminf(dmin[6], d6); dmin[7] = fminf(dmin[7], d7);
        }
    }

    // warp-reduce mins (all lanes get global row min)
    float cut[8];
#pragma unroll
    for (int r = 0; r < 8; r++) {
        float v = dmin[r];
        for (int o = 16; o; o >>= 1)
            v = fminf(v, __shfl_xor_sync(0xffffffffu, v, o));
        dmin[r] = v;
        cut[r] = v + 0.88f;   // exp(-100*0.88) underflows fp32: matches reference zeros
    }

    // ---------------- sweep 2: bit-identical recompute, sparse hits -----------
    for (int tile = 0; tile < K_CODES / TK; ++tile) {
        __syncthreads();
#pragma unroll
        for (int j = 0; j < 9; j++) {
            float v = g_cbp[j * K_CODES + tile * TK + tid];
            ((float2*)s_cb[j])[tid] = make_float2(v, v);
        }
        __syncthreads();
#pragma unroll 2
        for (int s = 0; s < TK / 32; s++) {
            int off = (s * 32 + lane) * 2;
            int k   = tile * TK + s * 32 + lane;
            unsigned long long ee2 = *(const unsigned long long*)&s_cb[8][off];
            unsigned long long a0 = ee2, a1 = ee2, a2 = ee2, a3 = ee2;
#pragma unroll
            for (int j = 0; j < 8; j++) {
                unsigned long long ej = *(const unsigned long long*)&s_cb[j][off];
                a0 = ffma2(z2[0][j], ej, a0);
                a1 = ffma2(z2[1][j], ej, a1);
                a2 = ffma2(z2[2][j], ej, a2);
                a3 = ffma2(z2[3][j], ej, a3);
            }
            float d[8];
            upk2(a0, d[0], d[1]); upk2(a1, d[2], d[3]);
            upk2(a2, d[4], d[5]); upk2(a3, d[6], d[7]);

            bool h = (d[0] < cut[0]) | (d[1] < cut[1]) | (d[2] < cut[2]) |
                     (d[3] < cut[3]) | (d[4] < cut[4]) | (d[5] < cut[5]) |
                     (d[6] < cut[6]) | (d[7] < cut[7]);
            if (h) {  // rare: only codes within 0.88 of the row min
#pragma unroll
                for (int r = 0; r < 8; r++) {
                    if (d[r] < cut[r]) {
                        int row = rowBase + w * 8 + r;
                        float diff = d[r] - dmin[r];          // == 0 exactly at argmin
                        if (diff == 0.f) atomicMin(&g_idx[row], k);
                        float arg = -100.f * diff;            // flat - max
                        float e = __expf(arg);
                        atomicAdd(&g_S1[row], e);
                        atomicAdd(&g_S2[row], e * arg);
                        int pos = atomicAdd(&g_cnt[row], 1);
                        if (pos < CAP) {
                            g_candk[row * CAP + pos] = k;
                            g_cande[row * CAP + pos] = e;
                        }
                    }
                }
            }
        }
    }
}

// ---------------- pass 3: per-row finalize (1 warp per row) -------------------
__global__ void k_post(const float* __restrict__ z, const float* __restrict__ cb,
                       float* __restrict__ out) {
    int gw   = (blockIdx.x * blockDim.x + threadIdx.x) >> 5;
    int lane = threadIdx.x & 31;
    if (gw >= N_ROWS) return;

    float S1 = g_S1[gw], S2 = g_S2[gw];
    int   c  = min(g_cnt[gw], CAP);
    float inv = 1.0f / (S1 * 8192.0f);
    for (int i = lane; i < c; i += 32)
        atomicAdd(&g_avg[g_candk[gw * CAP + i]], g_cande[gw * CAP + i] * inv);

    int idx = g_idx[gw];
    int b = gw >> 8, rem = gw & 255;
    float local = 0.f;
    if (lane < 8) {
        float q  = cb[idx * 8 + lane];
        float zv = z[b * 2048 + lane * 256 + rem];
        out[b * 2048 + lane * 256 + rem] = q;       // z_q (straight-through fwd)
        float df = q - zv;
        local = df * df;
    }
    local += __shfl_xor_sync(0xffffffffu, local, 1);
    local += __shfl_xor_sync(0xffffffffu, local, 2);
    local += __shfl_xor_sync(0xffffffffu, local, 4);
    if (lane == 0) {
        atomicAdd(&g_mse, local);
        atomicAdd(&g_sampleH, S2 / S1 - logf(S1)); // = sum p*logp for this row
        out[65537 + gw] = (float)idx;              // idx output as float
    }
}

// ---------------- pass 4: avg-entropy reduce + loss ---------------------------
__global__ void k_final(float* __restrict__ out) {
    __shared__ float red[256];
    float a = 0.f;
    for (int k = threadIdx.x; k < K_CODES; k += 256) {
        float av = g_avg[k];
        a += av * logf(av + 1e-5f);                // = -avg_entropy contribution
    }
    red[threadIdx.x] = a;
    __syncthreads();
    for (int s = 128; s; s >>= 1) {
        if (threadIdx.x < s) red[threadIdx.x] += red[threadIdx.x + s];
        __syncthreads();
    }
    if (threadIdx.x == 0) {
        float sample_entropy = -(g_sampleH / 8192.0f);
        float ent = 0.1f * (sample_entropy + red[0]);   // sample - avg_entropy
        out[65536] = 1.25f * g_mse / 65536.0f + ent;    // vq + beta*commit + ent
    }
}

// ---------------- launch ------------------------------------------------------
extern "C" void kernel_launch(void* const* d_in, const int* in_sizes, int n_in,
                              void* d_out, int out_size) {
    const float* z  = (const float*)d_in[0];
    const float* cb = (const float*)d_in[1];
    float* out = (float*)d_out;
    (void)in_sizes; (void)n_in; (void)out_size;

    k_zero<<<(K_CODES + 255) / 256, 256>>>();
    k_prep<<<(K_CODES + 255) / 256, 256>>>(cb);
    k_main<<<128, 256>>>(z);
    k_post<<<N_ROWS * 32 / 256, 256>>>(z, cb, out);
    k_final<<<1, 256>>>(out);
}

// round 2
// speedup vs baseline: 1.2471x; 1.2471x over previous
#include <cuda_runtime.h>

#define K_CODES 16384
#define N_ROWS  8192
#define CAP     1024
#define TK      256
#define KSPLIT  8
#define KRANGE  (K_CODES / KSPLIT)   // 2048

// ---------------- scratch (__device__ globals: no allocs allowed) -------------
__device__ float g_cbp[9 * K_CODES];     // SoA: j<8 -> -2*e_j[k]; j==8 -> sum e^2
__device__ float g_warm[N_ROWS];         // warm-start upper bound on row min
__device__ int   g_cnt[N_ROWS];
__device__ int2  g_cand[N_ROWS * CAP];   // (k, float_bits(d)) candidates
__device__ float g_avg[K_CODES];
__device__ float g_sampleH;
__device__ float g_mse;

// ---------------- f32x2 helpers ----------------------------------------------
static __device__ __forceinline__ unsigned long long pk2(float a, float b) {
    unsigned long long r;
    asm("mov.b64 %0, {%1, %2};" : "=l"(r) : "f"(a), "f"(b));
    return r;
}
static __device__ __forceinline__ void upk2(unsigned long long v, float& a, float& b) {
    asm("mov.b64 {%0, %1}, %2;" : "=f"(a), "=f"(b) : "l"(v));
}
static __device__ __forceinline__ unsigned long long ffma2(
    unsigned long long a, unsigned long long b, unsigned long long c) {
    unsigned long long d;
    asm("fma.rn.f32x2 %0, %1, %2, %3;" : "=l"(d) : "l"(a), "l"(b), "l"(c));
    return d;
}

// ---------------- pass 0: zero scratch + preprocess codebook ------------------
__global__ void k_init(const float* __restrict__ cb) {
    int t = blockIdx.x * 256 + threadIdx.x;       // grid 64 -> t < 16384
    if (t < N_ROWS) g_cnt[t] = 0;
    if (t == 0) { g_sampleH = 0.f; g_mse = 0.f; }
    if (t < K_CODES) {
        g_avg[t] = 0.f;
        float ss = 0.f;
#pragma unroll
        for (int j = 0; j < 8; j++) {
            float e = cb[t * 8 + j];
            g_cbp[j * K_CODES + t] = -2.f * e;
            ss += e * e;
        }
        g_cbp[8 * K_CODES + t] = ss;
    }
}

// ---------------- pass 1: warm-start min over first 512 codes -----------------
// 128 blocks x 256 thr; 64 rows/block, warp w owns rows w*8..w*8+7
__global__ __launch_bounds__(256) void k_warm(const float* __restrict__ z) {
    __shared__ __align__(16) float s_p[9][2 * 512];
    __shared__ float s_z[64 * 8];

    const int tid  = threadIdx.x;
    const int lane = tid & 31;
    const int w    = tid >> 5;
    const int rowBase = blockIdx.x * 64;

    for (int i = tid; i < 512; i += 256) {
        int ro = i >> 3, j = i & 7;
        int row = rowBase + ro;
        s_z[i] = z[(row >> 8) * 2048 + j * 256 + (row & 255)];
    }
    for (int i = tid; i < 512; i += 256) {
#pragma unroll
        for (int j = 0; j < 9; j++) {
            float v = g_cbp[j * K_CODES + i];     // probes = codes 0..511
            ((float2*)s_p[j])[i] = make_float2(v, v);
        }
    }
    __syncthreads();

    unsigned long long z2[4][8];
#pragma unroll
    for (int p = 0; p < 4; p++)
#pragma unroll
        for (int j = 0; j < 8; j++)
            z2[p][j] = pk2(s_z[(w * 8 + 2 * p) * 8 + j],
                           s_z[(w * 8 + 2 * p + 1) * 8 + j]);

    float dmin[8];
#pragma unroll
    for (int r = 0; r < 8; r++) dmin[r] = 3.4e38f;

#pragma unroll 2
    for (int s = 0; s < 16; s++) {
        int off = (s * 32 + lane) * 2;
        unsigned long long ee2 = *(const unsigned long long*)&s_p[8][off];
        unsigned long long a0 = ee2, a1 = ee2, a2 = ee2, a3 = ee2;
#pragma unroll
        for (int j = 0; j < 8; j++) {
            unsigned long long ej = *(const unsigned long long*)&s_p[j][off];
            a0 = ffma2(z2[0][j], ej, a0);
            a1 = ffma2(z2[1][j], ej, a1);
            a2 = ffma2(z2[2][j], ej, a2);
            a3 = ffma2(z2[3][j], ej, a3);
        }
        float d[8];
        upk2(a0, d[0], d[1]); upk2(a1, d[2], d[3]);
        upk2(a2, d[4], d[5]); upk2(a3, d[6], d[7]);
#pragma unroll
        for (int r = 0; r < 8; r++) dmin[r] = fminf(dmin[r], d[r]);
    }
#pragma unroll
    for (int r = 0; r < 8; r++) {
        float v = dmin[r];
        for (int o = 16; o; o >>= 1)
            v = fminf(v, __shfl_xor_sync(0xffffffffu, v, o));
        if (lane == 0) g_warm[rowBase + w * 8 + r] = v;
    }
}

// ---------------- pass 2: single sweep, static-cut candidate capture ----------
// grid (128 rowblocks, 8 ksplits) x 256 thr
__global__ __launch_bounds__(256, 2) void k_sweep(const float* __restrict__ z) {
    __shared__ __align__(16) float s_cb[9][2 * TK];
    __shared__ float s_z[64 * 8];

    const int tid  = threadIdx.x;
    const int lane = tid & 31;
    const int w    = tid >> 5;
    const int rowBase = blockIdx.x * 64;
    const int k0      = blockIdx.y * KRANGE;

    for (int i = tid; i < 512; i += 256) {
        int ro = i >> 3, j = i & 7;
        int row = rowBase + ro;
        s_z[i] = z[(row >> 8) * 2048 + j * 256 + (row & 255)];
    }
    __syncthreads();

    unsigned long long z2[4][8];
#pragma unroll
    for (int p = 0; p < 4; p++)
#pragma unroll
        for (int j = 0; j < 8; j++)
            z2[p][j] = pk2(s_z[(w * 8 + 2 * p) * 8 + j],
                           s_z[(w * 8 + 2 * p + 1) * 8 + j]);

    float cut[8];
#pragma unroll
    for (int r = 0; r < 8; r++)
        cut[r] = g_warm[rowBase + w * 8 + r] + 0.88f;  // exp(-100*0.88) == 0 in fp32

    for (int tile = 0; tile < KRANGE / TK; ++tile) {
        __syncthreads();
#pragma unroll
        for (int j = 0; j < 9; j++) {
            float v = g_cbp[j * K_CODES + k0 + tile * TK + tid];
            ((float2*)s_cb[j])[tid] = make_float2(v, v);
        }
        __syncthreads();
#pragma unroll 2
        for (int s = 0; s < TK / 32; s++) {
            int off = (s * 32 + lane) * 2;
            int k   = k0 + tile * TK + s * 32 + lane;
            unsigned long long ee2 = *(const unsigned long long*)&s_cb[8][off];
            unsigned long long a0 = ee2, a1 = ee2, a2 = ee2, a3 = ee2;
#pragma unroll
            for (int j = 0; j < 8; j++) {
                unsigned long long ej = *(const unsigned long long*)&s_cb[j][off];
                a0 = ffma2(z2[0][j], ej, a0);
                a1 = ffma2(z2[1][j], ej, a1);
                a2 = ffma2(z2[2][j], ej, a2);
                a3 = ffma2(z2[3][j], ej, a3);
            }
            float d[8];
            upk2(a0, d[0], d[1]); upk2(a1, d[2], d[3]);
            upk2(a2, d[4], d[5]); upk2(a3, d[6], d[7]);

            bool h = (d[0] < cut[0]) | (d[1] < cut[1]) | (d[2] < cut[2]) |
                     (d[3] < cut[3]) | (d[4] < cut[4]) | (d[5] < cut[5]) |
                     (d[6] < cut[6]) | (d[7] < cut[7]);
            if (h) {  // rare: ~0.2% of (row,code) pairs
#pragma unroll
                for (int r = 0; r < 8; r++) {
                    if (d[r] < cut[r]) {
                        int row = rowBase + w * 8 + r;
                        int pos = atomicAdd(&g_cnt[row], 1);
                        if (pos < CAP)
                            g_cand[row * CAP + pos] =
                                make_int2(k, __float_as_int(d[r]));
                    }
                }
            }
        }
    }
}

// ---------------- pass 3: per-row finalize over candidates (1 warp/row) ------
__global__ void k_finalize(const float* __restrict__ z,
                           const float* __restrict__ cb,
                           float* __restrict__ out) {
    int gw   = (blockIdx.x * blockDim.x + threadIdx.x) >> 5;
    int lane = threadIdx.x & 31;
    if (gw >= N_ROWS) return;

    int cnt = min(g_cnt[gw], CAP);

    // argmin with first-index tie-break: lexicographic (monotonic d bits, k)
    unsigned long long best = ~0ull;
    for (int i = lane; i < cnt; i += 32) {
        int2 c = g_cand[gw * CAP + i];
        unsigned b = (unsigned)c.y;
        unsigned m = (b & 0x80000000u) ? ~b : (b | 0x80000000u);
        unsigned long long key = ((unsigned long long)m << 32) | (unsigned)c.x;
        best = (key < best) ? key : best;
    }
    for (int o = 16; o; o >>= 1) {
        unsigned long long v = __shfl_xor_sync(0xffffffffu, best, o);
        best = (v < best) ? v : best;
    }
    int idx = (int)(unsigned)best;
    unsigned m = (unsigned)(best >> 32);
    unsigned db = (m & 0x80000000u) ? (m ^ 0x80000000u) : ~m;
    float dmin = __uint_as_float(db);

    float S1 = 0.f, S2 = 0.f;
    for (int i = lane; i < cnt; i += 32) {
        int2 c = g_cand[gw * CAP + i];
        float arg = -100.f * (__int_as_float(c.y) - dmin);
        float e = __expf(arg);
        S1 += e; S2 += e * arg;
    }
    for (int o = 16; o; o >>= 1) {
        S1 += __shfl_xor_sync(0xffffffffu, S1, o);
        S2 += __shfl_xor_sync(0xffffffffu, S2, o);
    }

    float inv = 1.0f / (S1 * 8192.0f);
    for (int i = lane; i < cnt; i += 32) {
        int2 c = g_cand[gw * CAP + i];
        float arg = -100.f * (__int_as_float(c.y) - dmin);
        float e = __expf(arg);
        if (e > 0.f) atomicAdd(&g_avg[c.x], e * inv);
    }

    int b = gw >> 8, rem = gw & 255;
    float local = 0.f;
    if (lane < 8) {
        float q  = cb[idx * 8 + lane];
        float zv = z[b * 2048 + lane * 256 + rem];
        out[b * 2048 + lane * 256 + rem] = q;       // z_q (straight-through fwd)
        float df = q - zv;
        local = df * df;
    }
    local += __shfl_xor_sync(0xffffffffu, local, 1);
    local += __shfl_xor_sync(0xffffffffu, local, 2);
    local += __shfl_xor_sync(0xffffffffu, local, 4);
    if (lane == 0) {
        atomicAdd(&g_mse, local);
        atomicAdd(&g_sampleH, S2 / S1 - logf(S1)); // = sum p*logp for this row
        out[65537 + gw] = (float)idx;              // idx output as float
    }
}

// ---------------- pass 4: avg-entropy reduce + loss ---------------------------
__global__ void k_final(float* __restrict__ out) {
    __shared__ float red[256];
    float a = 0.f;
    for (int k = threadIdx.x; k < K_CODES; k += 256) {
        float av = g_avg[k];
        a += av * logf(av + 1e-5f);                // = -avg_entropy contribution
    }
    red[threadIdx.x] = a;
    __syncthreads();
    for (int s = 128; s; s >>= 1) {
        if (threadIdx.x < s) red[threadIdx.x] += red[threadIdx.x + s];
        __syncthreads();
    }
    if (threadIdx.x == 0) {
        float sample_entropy = -(g_sampleH / 8192.0f);
        float ent = 0.1f * (sample_entropy + red[0]);   // sample - avg_entropy
        out[65536] = 1.25f * g_mse / 65536.0f + ent;    // vq + beta*commit + ent
    }
}

// ---------------- launch ------------------------------------------------------
extern "C" void kernel_launch(void* const* d_in, const int* in_sizes, int n_in,
                              void* d_out, int out_size) {
    const float* z  = (const float*)d_in[0];
    const float* cb = (const float*)d_in[1];
    float* out = (float*)d_out;
    (void)in_sizes; (void)n_in; (void)out_size;

    k_init<<<64, 256>>>(cb);
    k_warm<<<128, 256>>>(z);
    k_sweep<<<dim3(128, KSPLIT), 256>>>(z);
    k_finalize<<<N_ROWS * 32 / 256, 256>>>(z, cb, out);
    k_final<<<1, 256>>>(out);
}

// round 3
// speedup vs baseline: 1.4035x; 1.1254x over previous
#include <cuda_runtime.h>

#define K_CODES 16384
#define N_ROWS  8192
#define CAP     1024
#define TK      256
#define KSPLIT  8
#define KRANGE  (K_CODES / KSPLIT)   // 2048
#define PROBES  1024

// ---------------- scratch (__device__ globals: no allocs allowed) -------------
__device__ float g_cbp[9 * K_CODES];     // SoA: j<8 -> -2*e_j[k]; j==8 -> sum e^2
__device__ float g_warm[N_ROWS];         // warm-start upper bound on row min
__device__ int   g_cnt[N_ROWS];
__device__ int2  g_cand[N_ROWS * CAP];   // (k, float_bits(d)) candidates
__device__ float g_avg[K_CODES];
__device__ float g_sampleH;
__device__ float g_mse;

// ---------------- f32x2 helpers ----------------------------------------------
static __device__ __forceinline__ unsigned long long pk2(float a, float b) {
    unsigned long long r;
    asm("mov.b64 %0, {%1, %2};" : "=l"(r) : "f"(a), "f"(b));
    return r;
}
static __device__ __forceinline__ void upk2(unsigned long long v, float& a, float& b) {
    asm("mov.b64 {%0, %1}, %2;" : "=f"(a), "=f"(b) : "l"(v));
}
static __device__ __forceinline__ unsigned long long ffma2(
    unsigned long long a, unsigned long long b, unsigned long long c) {
    unsigned long long d;
    asm("fma.rn.f32x2 %0, %1, %2, %3;" : "=l"(d) : "l"(a), "l"(b), "l"(c));
    return d;
}

// ---------------- pass 0: zero scratch + preprocess codebook ------------------
__global__ void k_init(const float* __restrict__ cb) {
    int t = blockIdx.x * 256 + threadIdx.x;       // grid 64 -> t < 16384
    if (t < N_ROWS) g_cnt[t] = 0;
    if (t == 0) { g_sampleH = 0.f; g_mse = 0.f; }
    if (t < K_CODES) {
        g_avg[t] = 0.f;
        float ss = 0.f;
#pragma unroll
        for (int j = 0; j < 8; j++) {
            float e = cb[t * 8 + j];
            g_cbp[j * K_CODES + t] = -2.f * e;
            ss += e * e;
        }
        g_cbp[8 * K_CODES + t] = ss;
    }
}

// ---------------- pass 1: warm-start min over first PROBES codes --------------
// 128 blocks x 256 thr; 64 rows/block, warp w owns rows w*8..w*8+7
__global__ __launch_bounds__(256, 2) void k_warm(const float* __restrict__ z) {
    __shared__ __align__(16) float s_cb[9][2 * TK];
    __shared__ float s_z[64 * 8];

    const int tid  = threadIdx.x;
    const int lane = tid & 31;
    const int w    = tid >> 5;
    const int rowBase = blockIdx.x * 64;

    for (int i = tid; i < 512; i += 256) {
        int ro = i >> 3, j = i & 7;
        int row = rowBase + ro;
        s_z[i] = z[(row >> 8) * 2048 + j * 256 + (row & 255)];
    }
    __syncthreads();

    unsigned long long z2[4][8];
#pragma unroll
    for (int p = 0; p < 4; p++)
#pragma unroll
        for (int j = 0; j < 8; j++)
            z2[p][j] = pk2(s_z[(w * 8 + 2 * p) * 8 + j],
                           s_z[(w * 8 + 2 * p + 1) * 8 + j]);

    float dmin[8];
#pragma unroll
    for (int r = 0; r < 8; r++) dmin[r] = 3.4e38f;

    for (int tile = 0; tile < PROBES / TK; ++tile) {
        __syncthreads();
#pragma unroll
        for (int j = 0; j < 9; j++) {
            float v = g_cbp[j * K_CODES + tile * TK + tid];
            ((float2*)s_cb[j])[tid] = make_float2(v, v);
        }
        __syncthreads();
#pragma unroll 2
        for (int s = 0; s < TK / 32; s++) {
            int off = (s * 32 + lane) * 2;
            unsigned long long ee2 = *(const unsigned long long*)&s_cb[8][off];
            unsigned long long a0 = ee2, a1 = ee2, a2 = ee2, a3 = ee2;
#pragma unroll
            for (int j = 0; j < 8; j++) {
                unsigned long long ej = *(const unsigned long long*)&s_cb[j][off];
                a0 = ffma2(z2[0][j], ej, a0);
                a1 = ffma2(z2[1][j], ej, a1);
                a2 = ffma2(z2[2][j], ej, a2);
                a3 = ffma2(z2[3][j], ej, a3);
            }
            float d[8];
            upk2(a0, d[0], d[1]); upk2(a1, d[2], d[3]);
            upk2(a2, d[4], d[5]); upk2(a3, d[6], d[7]);
#pragma unroll
            for (int r = 0; r < 8; r++) dmin[r] = fminf(dmin[r], d[r]);
        }
    }
#pragma unroll
    for (int r = 0; r < 8; r++) {
        float v = dmin[r];
        for (int o = 16; o; o >>= 1)
            v = fminf(v, __shfl_xor_sync(0xffffffffu, v, o));
        if (lane == 0) g_warm[rowBase + w * 8 + r] = v;
    }
}

// ---------------- dummy launch so ncu (-s 5) profiles k_sweep next ------------
__global__ void k_nop() {}

// ---------------- pass 2: single sweep, ballot-aggregated capture -------------
// grid (128 rowblocks, 8 ksplits) x 256 thr
__global__ __launch_bounds__(256, 2) void k_sweep(const float* __restrict__ z) {
    __shared__ __align__(16) float s_cb[9][2 * TK];
    __shared__ float s_z[64 * 8];

    const int tid  = threadIdx.x;
    const int lane = tid & 31;
    const int w    = tid >> 5;
    const int rowBase = blockIdx.x * 64;
    const int k0      = blockIdx.y * KRANGE;
    const unsigned lmask = (1u << lane) - 1u;

    for (int i = tid; i < 512; i += 256) {
        int ro = i >> 3, j = i & 7;
        int row = rowBase + ro;
        s_z[i] = z[(row >> 8) * 2048 + j * 256 + (row & 255)];
    }
    __syncthreads();

    unsigned long long z2[4][8];
#pragma unroll
    for (int p = 0; p < 4; p++)
#pragma unroll
        for (int j = 0; j < 8; j++)
            z2[p][j] = pk2(s_z[(w * 8 + 2 * p) * 8 + j],
                           s_z[(w * 8 + 2 * p + 1) * 8 + j]);

    float cut[8];
#pragma unroll
    for (int r = 0; r < 8; r++)
        cut[r] = g_warm[rowBase + w * 8 + r] + 0.88f;  // exp(-100*0.88) == 0 fp32

    for (int tile = 0; tile < KRANGE / TK; ++tile) {
        __syncthreads();
#pragma unroll
        for (int j = 0; j < 9; j++) {
            float v = g_cbp[j * K_CODES + k0 + tile * TK + tid];
            ((float2*)s_cb[j])[tid] = make_float2(v, v);
        }
        __syncthreads();
#pragma unroll 2
        for (int s = 0; s < TK / 32; s++) {
            int off = (s * 32 + lane) * 2;
            int k   = k0 + tile * TK + s * 32 + lane;
            unsigned long long ee2 = *(const unsigned long long*)&s_cb[8][off];
            unsigned long long a0 = ee2, a1 = ee2, a2 = ee2, a3 = ee2;
#pragma unroll
            for (int j = 0; j < 8; j++) {
                unsigned long long ej = *(const unsigned long long*)&s_cb[j][off];
                a0 = ffma2(z2[0][j], ej, a0);
                a1 = ffma2(z2[1][j], ej, a1);
                a2 = ffma2(z2[2][j], ej, a2);
                a3 = ffma2(z2[3][j], ej, a3);
            }
            float d[8];
            upk2(a0, d[0], d[1]); upk2(a1, d[2], d[3]);
            upk2(a2, d[4], d[5]); upk2(a3, d[6], d[7]);

            // warp-uniform hit handling: ballots in converged flow
            unsigned bal[8];
#pragma unroll
            for (int r = 0; r < 8; r++)
                bal[r] = __ballot_sync(0xffffffffu, d[r] < cut[r]);
#pragma unroll
            for (int r = 0; r < 8; r++) {
                if (bal[r]) {                    // uniform branch (no divergence)
                    int row = rowBase + w * 8 + r;
                    int n = __popc(bal[r]);
                    int pos = 0;
                    if (lane == 0) pos = atomicAdd(&g_cnt[row], n);
                    pos = __shfl_sync(0xffffffffu, pos, 0);
                    if (d[r] < cut[r]) {         // tiny predicated store
                        int slot = pos + __popc(bal[r] & lmask);
                        if (slot < CAP)
                            g_cand[row * CAP + slot] =
                                make_int2(k, __float_as_int(d[r]));
                    }
                }
            }
        }
    }
}

// ---------------- pass 3: per-row finalize, online softmax (1 warp/row) -------
__global__ void k_finalize(const float* __restrict__ z,
                           const float* __restrict__ cb,
                           float* __restrict__ out) {
    int gw   = (blockIdx.x * blockDim.x + threadIdx.x) >> 5;
    int lane = threadIdx.x & 31;
    if (gw >= N_ROWS) return;

    int cnt = min(g_cnt[gw], CAP);

    // online softmax state per lane
    float dmin = 1e30f, S1 = 0.f, S2 = 0.f;
    int   idx  = 0x7fffffff;
    for (int i = lane; i < cnt; i += 32) {
        int2 c = g_cand[gw * CAP + i];
        float d = __int_as_float(c.y);
        if (d < dmin) {
            float delta = -100.f * (dmin - d);     // <= 0, finite (dmin<=1e30)
            float sc = __expf(delta);
            S2 = sc * (S2 + delta * S1);
            S1 = sc * S1 + 1.f;
            dmin = d; idx = c.x;
        } else {
            float arg = -100.f * (d - dmin);
            float e = __expf(arg);
            S1 += e; S2 += e * arg;
            if (d == dmin) idx = min(idx, c.x);
        }
    }
    // warp merge
    for (int o = 16; o; o >>= 1) {
        float od  = __shfl_xor_sync(0xffffffffu, dmin, o);
        float oS1 = __shfl_xor_sync(0xffffffffu, S1, o);
        float oS2 = __shfl_xor_sync(0xffffffffu, S2, o);
        int   oix = __shfl_xor_sync(0xffffffffu, idx, o);
        float dlo = fminf(dmin, od);
        float da = -100.f * (dmin - dlo); float sa = __expf(da);
        float db = -100.f * (od  - dlo);  float sb = __expf(db);
        float nS2 = sa * (S2 + da * S1) + sb * (oS2 + db * oS1);
        float nS1 = sa * S1 + sb * oS1;
        int nidx;
        if (od < dmin)       nidx = oix;
        else if (od == dmin) nidx = min(idx, oix);
        else                 nidx = idx;
        dmin = dlo; S1 = nS1; S2 = nS2; idx = nidx;
    }

    // scatter avg_probs contributions (candidates hot in L1/L2 now)
    float inv = 1.0f / (S1 * 8192.0f);
    for (int i = lane; i < cnt; i += 32) {
        int2 c = g_cand[gw * CAP + i];
        float e = __expf(-100.f * (__int_as_float(c.y) - dmin));
        if (e > 0.f) atomicAdd(&g_avg[c.x], e * inv);
    }

    int b = gw >> 8, rem = gw & 255;
    float local = 0.f;
    if (lane < 8) {
        float q  = cb[idx * 8 + lane];
        float zv = z[b * 2048 + lane * 256 + rem];
        out[b * 2048 + lane * 256 + rem] = q;       // z_q (straight-through fwd)
        float df = q - zv;
        local = df * df;
    }
    local += __shfl_xor_sync(0xffffffffu, local, 1);
    local += __shfl_xor_sync(0xffffffffu, local, 2);
    local += __shfl_xor_sync(0xffffffffu, local, 4);
    if (lane == 0) {
        atomicAdd(&g_mse, local);
        atomicAdd(&g_sampleH, S2 / S1 - logf(S1)); // = sum p*logp for this row
        out[65537 + gw] = (float)idx;              // idx output as float
    }
}

// ---------------- pass 4: avg-entropy reduce + loss ---------------------------
__global__ void k_final(float* __restrict__ out) {
    __shared__ float red[256];
    float a = 0.f;
    for (int k = threadIdx.x; k < K_CODES; k += 256) {
        float av = g_avg[k];
        a += av * logf(av + 1e-5f);                // = -avg_entropy contribution
    }
    red[threadIdx.x] = a;
    __syncthreads();
    for (int s = 128; s; s >>= 1) {
        if (threadIdx.x < s) red[threadIdx.x] += red[threadIdx.x + s];
        __syncthreads();
    }
    if (threadIdx.x == 0) {
        float sample_entropy = -(g_sampleH / 8192.0f);
        float ent = 0.1f * (sample_entropy + red[0]);   // sample - avg_entropy
        out[65536] = 1.25f * g_mse / 65536.0f + ent;    // vq + beta*commit + ent
    }
}

// ---------------- launch ------------------------------------------------------
extern "C" void kernel_launch(void* const* d_in, const int* in_sizes, int n_in,
                              void* d_out, int out_size) {
    const float* z  = (const float*)d_in[0];
    const float* cb = (const float*)d_in[1];
    float* out = (float*)d_out;
    (void)in_sizes; (void)n_in; (void)out_size;

    k_init<<<64, 256>>>(cb);
    k_warm<<<128, 256>>>(z);
    k_nop<<<1, 32>>>();                       // shifts ncu's profiled launch onto k_sweep
    k_sweep<<<dim3(128, KSPLIT), 256>>>(z);
    k_finalize<<<N_ROWS * 32 / 256, 256>>>(z, cb, out);
    k_final<<<1, 256>>>(out);
}

// round 4
// speedup vs baseline: 1.4057x; 1.0016x over previous
#include <cuda_runtime.h>

#define K_CODES 16384
#define N_ROWS  8192
#define CAP     1024
#define TK      256
#define KSPLIT  8
#define KRANGE  (K_CODES / KSPLIT)   // 2048
#define PROBES  1024

// ---------------- scratch (__device__ globals: no allocs allowed) -------------
__device__ float g_cbp[9 * K_CODES];          // SoA: -2e / sum e^2 (warm pass)
__device__ __align__(16) float g_cbd[9 * 2 * K_CODES];  // duplicated for f32x2
__device__ float g_warm[N_ROWS];
__device__ int   g_cnt[N_ROWS];
__device__ int2  g_cand[N_ROWS * CAP];
__device__ float g_avg[K_CODES];
__device__ float g_sampleH;
__device__ float g_mse;

// ---------------- helpers -----------------------------------------------------
static __device__ __forceinline__ unsigned long long pk2(float a, float b) {
    unsigned long long r;
    asm("mov.b64 %0, {%1, %2};" : "=l"(r) : "f"(a), "f"(b));
    return r;
}
static __device__ __forceinline__ void upk2(unsigned long long v, float& a, float& b) {
    asm("mov.b64 {%0, %1}, %2;" : "=f"(a), "=f"(b) : "l"(v));
}
static __device__ __forceinline__ unsigned long long ffma2(
    unsigned long long a, unsigned long long b, unsigned long long c) {
    unsigned long long d;
    asm("fma.rn.f32x2 %0, %1, %2, %3;" : "=l"(d) : "l"(a), "l"(b), "l"(c));
    return d;
}
static __device__ __forceinline__ void cp16(unsigned dst, const void* src) {
    asm volatile("cp.async.cg.shared.global [%0], [%1], 16;"
                 :: "r"(dst), "l"(src));
}

// ---------------- pass 0: zero scratch + preprocess codebook ------------------
__global__ void k_init(const float* __restrict__ cb) {
    int t = blockIdx.x * 256 + threadIdx.x;       // grid 64 -> t < 16384
    if (t < N_ROWS) g_cnt[t] = 0;
    if (t == 0) { g_sampleH = 0.f; g_mse = 0.f; }
    if (t < K_CODES) {
        g_avg[t] = 0.f;
        float ss = 0.f;
#pragma unroll
        for (int j = 0; j < 8; j++) {
            float e = cb[t * 8 + j];
            float v = -2.f * e;
            g_cbp[j * K_CODES + t] = v;
            g_cbd[j * 2 * K_CODES + 2 * t]     = v;
            g_cbd[j * 2 * K_CODES + 2 * t + 1] = v;
            ss += e * e;
        }
        g_cbp[8 * K_CODES + t] = ss;
        g_cbd[8 * 2 * K_CODES + 2 * t]     = ss;
        g_cbd[8 * 2 * K_CODES + 2 * t + 1] = ss;
    }
}

// ---------------- pass 1: warm-start min over first PROBES codes --------------
__global__ __launch_bounds__(256, 2) void k_warm(const float* __restrict__ z) {
    __shared__ __align__(16) float s_cb[9][2 * TK];
    __shared__ float s_z[64 * 8];

    const int tid  = threadIdx.x;
    const int lane = tid & 31;
    const int w    = tid >> 5;
    const int rowBase = blockIdx.x * 64;

    for (int i = tid; i < 512; i += 256) {
        int ro = i >> 3, j = i & 7;
        int row = rowBase + ro;
        s_z[i] = z[(row >> 8) * 2048 + j * 256 + (row & 255)];
    }
    __syncthreads();

    unsigned long long z2[4][8];
#pragma unroll
    for (int p = 0; p < 4; p++)
#pragma unroll
        for (int j = 0; j < 8; j++)
            z2[p][j] = pk2(s_z[(w * 8 + 2 * p) * 8 + j],
                           s_z[(w * 8 + 2 * p + 1) * 8 + j]);

    float dmin[8];
#pragma unroll
    for (int r = 0; r < 8; r++) dmin[r] = 3.4e38f;

    for (int tile = 0; tile < PROBES / TK; ++tile) {
        __syncthreads();
#pragma unroll
        for (int j = 0; j < 9; j++) {
            float v = g_cbp[j * K_CODES + tile * TK + tid];
            ((float2*)s_cb[j])[tid] = make_float2(v, v);
        }
        __syncthreads();
#pragma unroll 2
        for (int s = 0; s < TK / 32; s++) {
            int off = (s * 32 + lane) * 2;
            unsigned long long ee2 = *(const unsigned long long*)&s_cb[8][off];
            unsigned long long a0 = ee2, a1 = ee2, a2 = ee2, a3 = ee2;
#pragma unroll
            for (int j = 0; j < 8; j++) {
                unsigned long long ej = *(const unsigned long long*)&s_cb[j][off];
                a0 = ffma2(z2[0][j], ej, a0);
                a1 = ffma2(z2[1][j], ej, a1);
                a2 = ffma2(z2[2][j], ej, a2);
                a3 = ffma2(z2[3][j], ej, a3);
            }
            float d[8];
            upk2(a0, d[0], d[1]); upk2(a1, d[2], d[3]);
            upk2(a2, d[4], d[5]); upk2(a3, d[6], d[7]);
#pragma unroll
            for (int r = 0; r < 8; r++) dmin[r] = fminf(dmin[r], d[r]);
        }
    }
#pragma unroll
    for (int r = 0; r < 8; r++) {
        float v = dmin[r];
        for (int o = 16; o; o >>= 1)
            v = fminf(v, __shfl_xor_sync(0xffffffffu, v, o));
        if (lane == 0) g_warm[rowBase + w * 8 + r] = v;
    }
}

// ---------------- dummy launch so ncu profiles k_sweep as launch #4 -----------
__global__ void k_nop() {}

// ---------------- pass 2: single sweep, cp.async double-buffered --------------
// grid (128 rowblocks, 8 ksplits) x 256 thr
__global__ __launch_bounds__(256, 2) void k_sweep(const float* __restrict__ z) {
    __shared__ __align__(16) float s_cb[2][9][2 * TK];
    __shared__ float s_z[64 * 8];

    const int tid  = threadIdx.x;
    const int lane = tid & 31;
    const int w    = tid >> 5;
    const int rowBase = blockIdx.x * 64;
    const int k0      = blockIdx.y * KRANGE;
    const unsigned lmask = (1u << lane) - 1u;
    const int NT = KRANGE / TK;                 // 8 tiles

    // stage z rows
    for (int i = tid; i < 512; i += 256) {
        int ro = i >> 3, j = i & 7;
        int row = rowBase + ro;
        s_z[i] = z[(row >> 8) * 2048 + j * 256 + (row & 255)];
    }

    // prologue: async-load tile 0  (1152 x 16B chunks; 128 chunks per j-row)
    {
        const int t = 0;
#pragma unroll
        for (int i = tid; i < 1152; i += 256) {
            int j = i >> 7, c = i & 127;
            unsigned dst = (unsigned)__cvta_generic_to_shared(&s_cb[0][j][c * 4]);
            cp16(dst, g_cbd + (size_t)j * (2 * K_CODES) + (size_t)(k0 + t * TK) * 2 + c * 4);
        }
        asm volatile("cp.async.commit_group;");
    }
    __syncthreads();

    unsigned long long z2[4][8];
#pragma unroll
    for (int p = 0; p < 4; p++)
#pragma unroll
        for (int j = 0; j < 8; j++)
            z2[p][j] = pk2(s_z[(w * 8 + 2 * p) * 8 + j],
                           s_z[(w * 8 + 2 * p + 1) * 8 + j]);

    float cut[8];
#pragma unroll
    for (int r = 0; r < 8; r++)
        cut[r] = g_warm[rowBase + w * 8 + r] + 0.88f;  // exp(-100*0.88)==0 fp32

    for (int t = 0; t < NT; ++t) {
        if (t + 1 < NT) {          // stream next tile into the other buffer
            int p = (t + 1) & 1;
#pragma unroll
            for (int i = tid; i < 1152; i += 256) {
                int j = i >> 7, c = i & 127;
                unsigned dst = (unsigned)__cvta_generic_to_shared(&s_cb[p][j][c * 4]);
                cp16(dst, g_cbd + (size_t)j * (2 * K_CODES) +
                          (size_t)(k0 + (t + 1) * TK) * 2 + c * 4);
            }
            asm volatile("cp.async.commit_group;");
            asm volatile("cp.async.wait_group 1;");
        } else {
            asm volatile("cp.async.wait_group 0;");
        }
        __syncthreads();           // tile t visible to all threads

        const float (*cb)[2 * TK] = s_cb[t & 1];
#pragma unroll 2
        for (int s = 0; s < TK / 32; s++) {
            int off = (s * 32 + lane) * 2;
            int k   = k0 + t * TK + s * 32 + lane;
            unsigned long long ee2 = *(const unsigned long long*)&cb[8][off];
            unsigned long long a0 = ee2, a1 = ee2, a2 = ee2, a3 = ee2;
#pragma unroll
            for (int j = 0; j < 8; j++) {
                unsigned long long ej = *(const unsigned long long*)&cb[j][off];
                a0 = ffma2(z2[0][j], ej, a0);
                a1 = ffma2(z2[1][j], ej, a1);
                a2 = ffma2(z2[2][j], ej, a2);
                a3 = ffma2(z2[3][j], ej, a3);
            }
            float d[8];
            upk2(a0, d[0], d[1]); upk2(a1, d[2], d[3]);
            upk2(a2, d[4], d[5]); upk2(a3, d[6], d[7]);

            unsigned bal[8], any = 0;
#pragma unroll
            for (int r = 0; r < 8; r++) {
                bal[r] = __ballot_sync(0xffffffffu, d[r] < cut[r]);
                any |= bal[r];
            }
            if (any) {                            // one uniform branch, ~30% taken
#pragma unroll
                for (int r = 0; r < 8; r++) {
                    if (bal[r]) {
                        int row = rowBase + w * 8 + r;
                        int n = __popc(bal[r]);
                        int pos = 0;
                        if (lane == 0) pos = atomicAdd(&g_cnt[row], n);
                        pos = __shfl_sync(0xffffffffu, pos, 0);
                        if (d[r] < cut[r]) {
                            int slot = pos + __popc(bal[r] & lmask);
                            if (slot < CAP)
                                g_cand[row * CAP + slot] =
                                    make_int2(k, __float_as_int(d[r]));
                        }
                    }
                }
            }
        }
        __syncthreads();           // before buffer t&1 is overwritten next iter
    }
}

// ---------------- pass 3: per-row finalize, online softmax (1 warp/row) -------
__global__ void k_finalize(const float* __restrict__ z,
                           const float* __restrict__ cb,
                           float* __restrict__ out) {
    int gw   = (blockIdx.x * blockDim.x + threadIdx.x) >> 5;
    int lane = threadIdx.x & 31;
    if (gw >= N_ROWS) return;

    int cnt = min(g_cnt[gw], CAP);

    float dmin = 1e30f, S1 = 0.f, S2 = 0.f;
    int   idx  = 0x7fffffff;
    for (int i = lane; i < cnt; i += 32) {
        int2 c = g_cand[gw * CAP + i];
        float d = __int_as_float(c.y);
        if (d < dmin) {
            float delta = -100.f * (dmin - d);
            float sc = __expf(delta);
            S2 = sc * (S2 + delta * S1);
            S1 = sc * S1 + 1.f;
            dmin = d; idx = c.x;
        } else {
            float arg = -100.f * (d - dmin);
            float e = __expf(arg);
            S1 += e; S2 += e * arg;
            if (d == dmin) idx = min(idx, c.x);
        }
    }
    for (int o = 16; o; o >>= 1) {
        float od  = __shfl_xor_sync(0xffffffffu, dmin, o);
        float oS1 = __shfl_xor_sync(0xffffffffu, S1, o);
        float oS2 = __shfl_xor_sync(0xffffffffu, S2, o);
        int   oix = __shfl_xor_sync(0xffffffffu, idx, o);
        float dlo = fminf(dmin, od);
        float da = -100.f * (dmin - dlo); float sa = __expf(da);
        float db = -100.f * (od  - dlo);  float sb = __expf(db);
        float nS2 = sa * (S2 + da * S1) + sb * (oS2 + db * oS1);
        float nS1 = sa * S1 + sb * oS1;
        int nidx;
        if (od < dmin)       nidx = oix;
        else if (od == dmin) nidx = min(idx, oix);
        else                 nidx = idx;
        dmin = dlo; S1 = nS1; S2 = nS2; idx = nidx;
    }

    float inv = 1.0f / (S1 * 8192.0f);
    for (int i = lane; i < cnt; i += 32) {
        int2 c = g_cand[gw * CAP + i];
        float e = __expf(-100.f * (__int_as_float(c.y) - dmin));
        if (e > 0.f) atomicAdd(&g_avg[c.x], e * inv);
    }

    int b = gw >> 8, rem = gw & 255;
    float local = 0.f;
    if (lane < 8) {
        float q  = cb[idx * 8 + lane];
        float zv = z[b * 2048 + lane * 256 + rem];
        out[b * 2048 + lane * 256 + rem] = q;
        float df = q - zv;
        local = df * df;
    }
    local += __shfl_xor_sync(0xffffffffu, local, 1);
    local += __shfl_xor_sync(0xffffffffu, local, 2);
    local += __shfl_xor_sync(0xffffffffu, local, 4);
    if (lane == 0) {
        atomicAdd(&g_mse, local);
        atomicAdd(&g_sampleH, S2 / S1 - logf(S1));
        out[65537 + gw] = (float)idx;
    }
}

// ---------------- pass 4: avg-entropy reduce + loss ---------------------------
__global__ void k_final(float* __restrict__ out) {
    __shared__ float red[256];
    float a = 0.f;
    for (int k = threadIdx.x; k < K_CODES; k += 256) {
        float av = g_avg[k];
        a += av * logf(av + 1e-5f);
    }
    red[threadIdx.x] = a;
    __syncthreads();
    for (int s = 128; s; s >>= 1) {
        if (threadIdx.x < s) red[threadIdx.x] += red[threadIdx.x + s];
        __syncthreads();
    }
    if (threadIdx.x == 0) {
        float sample_entropy = -(g_sampleH / 8192.0f);
        float ent = 0.1f * (sample_entropy + red[0]);
        out[65536] = 1.25f * g_mse / 65536.0f + ent;
    }
}

// ---------------- launch ------------------------------------------------------
extern "C" void kernel_launch(void* const* d_in, const int* in_sizes, int n_in,
                              void* d_out, int out_size) {
    const float* z  = (const float*)d_in[0];
    const float* cb = (const float*)d_in[1];
    float* out = (float*)d_out;
    (void)in_sizes; (void)n_in; (void)out_size;

    k_init<<<64, 256>>>(cb);
    k_warm<<<128, 256>>>(z);
    k_nop<<<1, 32>>>();                       // keeps k_sweep as ncu's profiled launch
    k_sweep<<<dim3(128, KSPLIT), 256>>>(z);
    k_finalize<<<N_ROWS * 32 / 256, 256>>>(z, cb, out);
    k_final<<<1, 256>>>(out);
}